// round 7
// baseline (speedup 1.0000x reference)
#include <cuda_runtime.h>
#include <stdint.h>
#include <math.h>

#define BATCH  4
#define SEQ    2048
#define DMODEL 1024
#define NHEAD  16
#define HDIM   64
#define NBH    (BATCH * NHEAD)        // 64
#define NTOK   (BATCH * SEQ)          // 8192
#define PROJ_ELEMS ((size_t)NTOK * DMODEL)  // 8388608
#define NROWS  ((size_t)NBH * SEQ)    // 131072 attention rows
#define NTILES 16                     // 2048 / 128

// qh, kh, vhT, ctx, fcb (each PROJ_ELEMS) + WqT + WfcT (1M each)
// + mstats, lstats, corr (NROWS*16 each = 2M floats each)
__device__ float g_scratch[5 * PROJ_ELEMS + 2 * 1024 * 1024 + 3 * NROWS * NTILES];

// ===================== helpers ==============================================
__device__ __forceinline__ uint32_t smem_u32(const void* p) {
    uint32_t a;
    asm("{ .reg .u64 t; cvta.to.shared.u64 t, %1; cvt.u32.u64 %0, t; }"
        : "=r"(a) : "l"(p));
    return a;
}
__device__ __forceinline__ void cp16(void* s, const void* g) {
    asm volatile("cp.async.cg.shared.global [%0], [%1], 16;"
                 :: "r"(smem_u32(s)), "l"(g));
}
__device__ __forceinline__ void cp_commit() {
    asm volatile("cp.async.commit_group;");
}
template <int N>
__device__ __forceinline__ void cp_wait() {
    asm volatile("cp.async.wait_group %0;" :: "n"(N));
}
__device__ __forceinline__ uint32_t f2tf(float x) {
    uint32_t r;
    asm("cvt.rn.tf32.f32 %0, %1;" : "=r"(r) : "f"(x));
    return r;
}
__device__ __forceinline__ void mma_tf32(float* d, const uint32_t* a,
                                         const uint32_t* b) {
    asm volatile(
        "mma.sync.aligned.m16n8k8.row.col.f32.tf32.tf32.f32 "
        "{%0,%1,%2,%3}, {%4,%5,%6,%7}, {%8,%9}, {%0,%1,%2,%3};"
        : "+f"(d[0]), "+f"(d[1]), "+f"(d[2]), "+f"(d[3])
        : "r"(a[0]), "r"(a[1]), "r"(a[2]), "r"(a[3]), "r"(b[0]), "r"(b[1]));
}
__device__ __forceinline__ float quadMax(float v) {
    v = fmaxf(v, __shfl_xor_sync(0xffffffffu, v, 1));
    v = fmaxf(v, __shfl_xor_sync(0xffffffffu, v, 2));
    return v;
}
__device__ __forceinline__ float quadSum(float v) {
    v += __shfl_xor_sync(0xffffffffu, v, 1);
    v += __shfl_xor_sync(0xffffffffu, v, 2);
    return v;
}

// ===================== tf32 mma.sync GEMM (proj / fc) =======================
// D[m][n] = sum_k A[m][k] * B[n][k]
enum { EPI_PROJ = 0, EPI_PROJV = 1, EPI_PLAIN = 4 };

template <int BN, int EPI>
__global__ __launch_bounds__(256, 2) void tc_gemm(
    const float* __restrict__ A, const float* __restrict__ B,
    const float* __restrict__ bias, float* __restrict__ C,
    int K, int lda, int ldb)
{
    constexpr int BM = 128, BK = 16;
    constexpr int LDS_ = BK + 4;
    constexpr int WARPS_M = 2;
    constexpr int WARPS_N = 4;
    constexpr int WM = BM / WARPS_M;             // 64
    constexpr int WN = BN / WARPS_N;             // 32
    constexpr int MT = WM / 16;                  // 4
    constexpr int NT = WN / 8;                   // 4

    __shared__ float As[2][BM * LDS_];
    __shared__ float Bs[2][BN * LDS_];

    const int tid  = threadIdx.x;
    const int warp = tid >> 5;
    const int lane = tid & 31;
    const int g    = lane >> 2;
    const int tig  = lane & 3;
    const int warp_m = warp / WARPS_N;
    const int warp_n = warp % WARPS_N;
    const int m0 = blockIdx.y * BM;
    const int n0 = blockIdx.x * BN;

    const float* Ag = A;
    const float* Bg = B;

    const int lr  = tid >> 2;
    const int lc4 = tid & 3;

    float acc[MT][NT][4];
#pragma unroll
    for (int i = 0; i < MT; i++)
#pragma unroll
        for (int j = 0; j < NT; j++)
#pragma unroll
            for (int r = 0; r < 4; r++) acc[i][j][r] = 0.f;

    const int nit = K / BK;

    auto load_stage = [&](int s, int k0) {
        cp16(&As[s][lr * LDS_ + lc4 * 4],
             Ag + (size_t)(m0 + lr) * lda + k0 + lc4 * 4);
        cp16(&As[s][(lr + 64) * LDS_ + lc4 * 4],
             Ag + (size_t)(m0 + lr + 64) * lda + k0 + lc4 * 4);
        cp16(&Bs[s][lr * LDS_ + lc4 * 4],
             Bg + (size_t)(n0 + lr) * ldb + k0 + lc4 * 4);
        cp16(&Bs[s][(lr + 64) * LDS_ + lc4 * 4],
             Bg + (size_t)(n0 + lr + 64) * ldb + k0 + lc4 * 4);
        cp_commit();
    };

    load_stage(0, 0);

    for (int it = 0; it < nit; it++) {
        if (it + 1 < nit) {
            load_stage((it + 1) & 1, (it + 1) * BK);
            cp_wait<1>();
        } else {
            cp_wait<0>();
        }
        __syncthreads();

        const float* as = As[it & 1];
        const float* bs = Bs[it & 1];
#pragma unroll
        for (int kt = 0; kt < BK / 8; kt++) {
            uint32_t af[MT][4];
#pragma unroll
            for (int i = 0; i < MT; i++) {
                int r = warp_m * WM + i * 16;
                const float* p = as + (r + g) * LDS_ + kt * 8 + tig;
                af[i][0] = f2tf(p[0]);
                af[i][1] = f2tf(p[8 * LDS_]);
                af[i][2] = f2tf(p[4]);
                af[i][3] = f2tf(p[8 * LDS_ + 4]);
            }
            uint32_t bf[NT][2];
#pragma unroll
            for (int j = 0; j < NT; j++) {
                int n = warp_n * WN + j * 8;
                const float* p = bs + (n + g) * LDS_ + kt * 8 + tig;
                bf[j][0] = f2tf(p[0]);
                bf[j][1] = f2tf(p[4]);
            }
#pragma unroll
            for (int i = 0; i < MT; i++)
#pragma unroll
                for (int j = 0; j < NT; j++)
                    mma_tf32(acc[i][j], af[i], bf[j]);
        }
        __syncthreads();
    }

#pragma unroll
    for (int i = 0; i < MT; i++) {
        int r0 = m0 + warp_m * WM + i * 16 + g;
        int r1 = r0 + 8;
#pragma unroll
        for (int j = 0; j < NT; j++) {
            int c = n0 + warp_n * WN + j * 8 + tig * 2;
            float d0 = acc[i][j][0], d1 = acc[i][j][1];
            float d2 = acc[i][j][2], d3 = acc[i][j][3];

            if (EPI == EPI_PLAIN) {
                float2 bb = *(const float2*)(bias + c);
                *(float2*)(C + (size_t)r0 * DMODEL + c) =
                    make_float2(d0 + bb.x, d1 + bb.y);
                *(float2*)(C + (size_t)r1 * DMODEL + c) =
                    make_float2(d2 + bb.x, d3 + bb.y);
            } else if (EPI == EPI_PROJ) {
                float2 bb = *(const float2*)(bias + c);
                int h = c >> 6, dd = c & 63;
                {
                    int b = r0 >> 11, s = r0 & (SEQ - 1);
                    *(float2*)(C + ((((size_t)b * NHEAD + h) * SEQ + s) << 6) + dd) =
                        make_float2(d0 + bb.x, d1 + bb.y);
                }
                {
                    int b = r1 >> 11, s = r1 & (SEQ - 1);
                    *(float2*)(C + ((((size_t)b * NHEAD + h) * SEQ + s) << 6) + dd) =
                        make_float2(d2 + bb.x, d3 + bb.y);
                }
            } else {  // EPI_PROJV: vhT[b][h][d][s]
                float2 bb = *(const float2*)(bias + c);
                int h = c >> 6, dd = c & 63;
                {
                    int b = r0 >> 11, s = r0 & (SEQ - 1);
                    float* base = C + (((size_t)b * NHEAD + h) * HDIM + dd) * SEQ + s;
                    base[0]   = d0 + bb.x;
                    base[SEQ] = d1 + bb.y;
                }
                {
                    int b = r1 >> 11, s = r1 & (SEQ - 1);
                    float* base = C + (((size_t)b * NHEAD + h) * HDIM + dd) * SEQ + s;
                    base[0]   = d2 + bb.x;
                    base[SEQ] = d3 + bb.y;
                }
            }
        }
    }
}

// ===================== scores + tile-softmax stats ==========================
// Per (b,h): S = (qh @ kh^T) * 0.125, tile 128x128. Epilogue computes per-row
// tile max m_t and l_t = sum exp(s - m_t), writes P~ = exp(s - m_t) to attn,
// (m_t, l_t) to stats.
__global__ __launch_bounds__(256, 2) void scores_kernel(
    const float* __restrict__ qh, const float* __restrict__ kh,
    float* __restrict__ attn, float* __restrict__ mstats,
    float* __restrict__ lstats)
{
    constexpr int BM = 128, BN = 128, BK = 16;
    constexpr int LDS_ = BK + 4;
    constexpr int MT = 4, NT = 4;                // 2x4 warp grid, 64x32 warp tile

    __shared__ float As[2][BM * LDS_];
    __shared__ float Bs[2][BN * LDS_];
    __shared__ float shm[128][5];
    __shared__ float shl[128][5];

    const int tid  = threadIdx.x;
    const int warp = tid >> 5;
    const int lane = tid & 31;
    const int g    = lane >> 2;
    const int tig  = lane & 3;
    const int warp_m = warp >> 2;                // 0..1
    const int warp_n = warp & 3;                 // 0..3
    const int qbase = blockIdx.y * BM;
    const int n0 = blockIdx.x * BN;
    const int tn = blockIdx.x;
    const int z  = blockIdx.z;

    const float* Ag = qh + (size_t)z * SEQ * HDIM;
    const float* Bg = kh + (size_t)z * SEQ * HDIM;

    const int lr  = tid >> 2;
    const int lc4 = tid & 3;

    float acc[MT][NT][4];
#pragma unroll
    for (int i = 0; i < MT; i++)
#pragma unroll
        for (int j = 0; j < NT; j++)
#pragma unroll
            for (int r = 0; r < 4; r++) acc[i][j][r] = 0.f;

    auto load_stage = [&](int s, int k0) {
        cp16(&As[s][lr * LDS_ + lc4 * 4],
             Ag + (size_t)(qbase + lr) * HDIM + k0 + lc4 * 4);
        cp16(&As[s][(lr + 64) * LDS_ + lc4 * 4],
             Ag + (size_t)(qbase + lr + 64) * HDIM + k0 + lc4 * 4);
        cp16(&Bs[s][lr * LDS_ + lc4 * 4],
             Bg + (size_t)(n0 + lr) * HDIM + k0 + lc4 * 4);
        cp16(&Bs[s][(lr + 64) * LDS_ + lc4 * 4],
             Bg + (size_t)(n0 + lr + 64) * HDIM + k0 + lc4 * 4);
        cp_commit();
    };

    load_stage(0, 0);
#pragma unroll
    for (int it = 0; it < 4; it++) {             // K = 64
        if (it + 1 < 4) {
            load_stage((it + 1) & 1, (it + 1) * BK);
            cp_wait<1>();
        } else {
            cp_wait<0>();
        }
        __syncthreads();
        const float* as = As[it & 1];
        const float* bs = Bs[it & 1];
#pragma unroll
        for (int kt = 0; kt < 2; kt++) {
            uint32_t af[MT][4];
#pragma unroll
            for (int i = 0; i < MT; i++) {
                const float* p = as + (warp_m * 64 + i * 16 + g) * LDS_ + kt * 8 + tig;
                af[i][0] = f2tf(p[0]);
                af[i][1] = f2tf(p[8 * LDS_]);
                af[i][2] = f2tf(p[4]);
                af[i][3] = f2tf(p[8 * LDS_ + 4]);
            }
            uint32_t bf[NT][2];
#pragma unroll
            for (int j = 0; j < NT; j++) {
                const float* p = bs + (warp_n * 32 + j * 8 + g) * LDS_ + kt * 8 + tig;
                bf[j][0] = f2tf(p[0]);
                bf[j][1] = f2tf(p[4]);
            }
#pragma unroll
            for (int i = 0; i < MT; i++)
#pragma unroll
                for (int j = 0; j < NT; j++)
                    mma_tf32(acc[i][j], af[i], bf[j]);
        }
        __syncthreads();
    }

    // -------- epilogue: scale, tile-softmax stats, write P~ -----------------
#pragma unroll
    for (int i = 0; i < MT; i++)
#pragma unroll
        for (int j = 0; j < NT; j++)
#pragma unroll
            for (int r = 0; r < 4; r++) acc[i][j][r] *= 0.125f;

    // stage 1: per-row max within this warp's 32 cols
#pragma unroll
    for (int i = 0; i < MT; i++) {
        int rl0 = warp_m * 64 + i * 16 + g;
        int rl1 = rl0 + 8;
        float m0v = -3.4e38f, m1v = -3.4e38f;
#pragma unroll
        for (int j = 0; j < NT; j++) {
            m0v = fmaxf(m0v, fmaxf(acc[i][j][0], acc[i][j][1]));
            m1v = fmaxf(m1v, fmaxf(acc[i][j][2], acc[i][j][3]));
        }
        m0v = quadMax(m0v);
        m1v = quadMax(m1v);
        if (tig == 0) { shm[rl0][warp_n] = m0v; shm[rl1][warp_n] = m1v; }
    }
    __syncthreads();

    // stage 2: tile max, exponentiate in place, partial sums
#pragma unroll
    for (int i = 0; i < MT; i++) {
        int rl0 = warp_m * 64 + i * 16 + g;
        int rl1 = rl0 + 8;
        float M0 = fmaxf(fmaxf(shm[rl0][0], shm[rl0][1]),
                         fmaxf(shm[rl0][2], shm[rl0][3]));
        float M1 = fmaxf(fmaxf(shm[rl1][0], shm[rl1][1]),
                         fmaxf(shm[rl1][2], shm[rl1][3]));
        float l0 = 0.f, l1 = 0.f;
#pragma unroll
        for (int j = 0; j < NT; j++) {
            float e0 = __expf(acc[i][j][0] - M0);
            float e1 = __expf(acc[i][j][1] - M0);
            float e2 = __expf(acc[i][j][2] - M1);
            float e3 = __expf(acc[i][j][3] - M1);
            acc[i][j][0] = e0; acc[i][j][1] = e1;
            acc[i][j][2] = e2; acc[i][j][3] = e3;
            l0 += e0 + e1;
            l1 += e2 + e3;
        }
        l0 = quadSum(l0);
        l1 = quadSum(l1);
        if (tig == 0) { shl[rl0][warp_n] = l0; shl[rl1][warp_n] = l1; }
        if (warp_n == 0 && tig == 0) {
            mstats[((size_t)z * SEQ + qbase + rl0) * NTILES + tn] = M0;
            mstats[((size_t)z * SEQ + qbase + rl1) * NTILES + tn] = M1;
        }
    }
    __syncthreads();

    // stage 3: write tile l, write P~
    if (warp_n == 0 && tig == 0) {
#pragma unroll
        for (int i = 0; i < MT; i++) {
            int rl0 = warp_m * 64 + i * 16 + g;
            int rl1 = rl0 + 8;
            lstats[((size_t)z * SEQ + qbase + rl0) * NTILES + tn] =
                shl[rl0][0] + shl[rl0][1] + shl[rl0][2] + shl[rl0][3];
            lstats[((size_t)z * SEQ + qbase + rl1) * NTILES + tn] =
                shl[rl1][0] + shl[rl1][1] + shl[rl1][2] + shl[rl1][3];
        }
    }

    float* Cbase = attn + (size_t)z * SEQ * SEQ;
#pragma unroll
    for (int i = 0; i < MT; i++) {
        int r0 = qbase + warp_m * 64 + i * 16 + g;
        int r1 = r0 + 8;
#pragma unroll
        for (int j = 0; j < NT; j++) {
            int c = n0 + warp_n * 32 + j * 8 + tig * 2;
            *(float2*)(Cbase + (size_t)r0 * SEQ + c) =
                make_float2(acc[i][j][0], acc[i][j][1]);
            *(float2*)(Cbase + (size_t)r1 * SEQ + c) =
                make_float2(acc[i][j][2], acc[i][j][3]);
        }
    }
}

// ===================== combine: per-row corr factors ========================
__global__ __launch_bounds__(256) void combine_kernel(
    const float* __restrict__ mstats, const float* __restrict__ lstats,
    float* __restrict__ corr)
{
    size_t row = (size_t)blockIdx.x * 256 + threadIdx.x;
    float m[NTILES], l[NTILES];
    const float4* mp = (const float4*)(mstats + row * NTILES);
    const float4* lp = (const float4*)(lstats + row * NTILES);
#pragma unroll
    for (int t = 0; t < NTILES / 4; t++) {
        float4 a = mp[t];
        m[t * 4 + 0] = a.x; m[t * 4 + 1] = a.y; m[t * 4 + 2] = a.z; m[t * 4 + 3] = a.w;
        float4 b = lp[t];
        l[t * 4 + 0] = b.x; l[t * 4 + 1] = b.y; l[t * 4 + 2] = b.z; l[t * 4 + 3] = b.w;
    }
    float M = -3.4e38f;
#pragma unroll
    for (int t = 0; t < NTILES; t++) M = fmaxf(M, m[t]);
    float w[NTILES];
    float L = 0.f;
#pragma unroll
    for (int t = 0; t < NTILES; t++) {
        w[t] = __expf(m[t] - M);
        L += l[t] * w[t];
    }
    float invL = 1.f / L;
    float4* cp = (float4*)(corr + row * NTILES);
#pragma unroll
    for (int t = 0; t < NTILES / 4; t++)
        cp[t] = make_float4(w[t * 4 + 0] * invL, w[t * 4 + 1] * invL,
                            w[t * 4 + 2] * invL, w[t * 4 + 3] * invL);
}

// ===================== fused ctx: normalize attn + P @ V ====================
// Per CTA: 128 q-rows of one (b,h), all 64 d-cols, K = 2048 in chunks of 32.
// Reads P~ from attn, multiplies by corr (-> normalized P), writes P back to
// attn (final output), and accumulates ctx = P @ V via tf32 mma.
__global__ __launch_bounds__(256, 2) void ctx_fused_kernel(
    const float* __restrict__ vhT, const float* __restrict__ corr,
    float* __restrict__ attn, float* __restrict__ ctx)
{
    constexpr int LDP = 36;
    __shared__ float Ps[128 * LDP];
    __shared__ float Vs[64 * LDP];
    __shared__ float cs[128 * NTILES];

    const int tid  = threadIdx.x;
    const int warp = tid >> 5;
    const int lane = tid & 31;
    const int g    = lane >> 2;
    const int tig  = lane & 3;
    const int warp_m = warp >> 1;                // 0..3 (32 rows each)
    const int warp_n = warp & 1;                 // 0..1 (32 cols each)
    const int z  = blockIdx.y;                   // b*16+h
    const int m0 = blockIdx.x * 128;

    float* Sg = attn + (size_t)z * SEQ * SEQ + (size_t)m0 * SEQ;
    const float* Vg = vhT + (size_t)z * HDIM * SEQ;

    // corr block for these 128 rows
    {
        const float4* cg = (const float4*)(corr + ((size_t)z * SEQ + m0) * NTILES);
        float4* cd = (float4*)cs;
        cd[tid]       = cg[tid];
        cd[tid + 256] = cg[tid + 256];
    }

    const int r  = tid >> 1;                     // 0..127 (P rows)
    const int f4 = (tid & 1) * 4;                // float4 col base (0|4)
    const int vi = tid * 2;                      // V float4 linear idx base
    const int vd = vi >> 3;                      // 0..63
    const int vc = vi & 7;

    float acc[2][4][4];
#pragma unroll
    for (int i = 0; i < 2; i++)
#pragma unroll
        for (int j = 0; j < 4; j++)
#pragma unroll
            for (int q = 0; q < 4; q++) acc[i][j][q] = 0.f;

    float4 sreg[4];
    float4 vreg[2];
    auto ldS = [&](int c) {
#pragma unroll
        for (int i = 0; i < 4; i++)
            sreg[i] = *(const float4*)(Sg + (size_t)r * SEQ + c * 32 + (f4 + i) * 4);
    };
    auto ldV = [&](int c) {
#pragma unroll
        for (int i = 0; i < 2; i++)
            vreg[i] = *(const float4*)(Vg + (size_t)vd * SEQ + c * 32 + (vc + i) * 4);
    };

    ldS(0); ldV(0);
    __syncthreads();                             // cs ready

    for (int c = 0; c < SEQ / 32; c++) {
        float cv = cs[r * NTILES + (c >> 2)];
        // normalize, write attn, stage tf32 into SMEM
#pragma unroll
        for (int i = 0; i < 4; i++) {
            float4 p;
            p.x = sreg[i].x * cv; p.y = sreg[i].y * cv;
            p.z = sreg[i].z * cv; p.w = sreg[i].w * cv;
            *(float4*)(Sg + (size_t)r * SEQ + c * 32 + (f4 + i) * 4) = p;
            uint32_t* ps = (uint32_t*)&Ps[r * LDP + (f4 + i) * 4];
            asm volatile("st.shared.v4.b32 [%0], {%1, %2, %3, %4};"
                         :: "r"(smem_u32(ps)), "r"(f2tf(p.x)), "r"(f2tf(p.y)),
                            "r"(f2tf(p.z)), "r"(f2tf(p.w)));
        }
#pragma unroll
        for (int i = 0; i < 2; i++) {
            uint32_t* vs = (uint32_t*)&Vs[vd * LDP + (vc + i) * 4];
            asm volatile("st.shared.v4.b32 [%0], {%1, %2, %3, %4};"
                         :: "r"(smem_u32(vs)), "r"(f2tf(vreg[i].x)), "r"(f2tf(vreg[i].y)),
                            "r"(f2tf(vreg[i].z)), "r"(f2tf(vreg[i].w)));
        }
        __syncthreads();
        if (c + 1 < SEQ / 32) { ldS(c + 1); ldV(c + 1); }  // prefetch over mma
#pragma unroll
        for (int kt = 0; kt < 4; kt++) {
            uint32_t af[2][4];
#pragma unroll
            for (int i = 0; i < 2; i++) {
                const float* p = Ps + (warp_m * 32 + i * 16 + g) * LDP + kt * 8 + tig;
                af[i][0] = __float_as_uint(p[0]);
                af[i][1] = __float_as_uint(p[8 * LDP]);
                af[i][2] = __float_as_uint(p[4]);
                af[i][3] = __float_as_uint(p[8 * LDP + 4]);
            }
            uint32_t bf[4][2];
#pragma unroll
            for (int j = 0; j < 4; j++) {
                const float* p = Vs + (warp_n * 32 + j * 8 + g) * LDP + kt * 8 + tig;
                bf[j][0] = __float_as_uint(p[0]);
                bf[j][1] = __float_as_uint(p[4]);
            }
#pragma unroll
            for (int i = 0; i < 2; i++)
#pragma unroll
                for (int j = 0; j < 4; j++)
                    mma_tf32(acc[i][j], af[i], bf[j]);
        }
        __syncthreads();
    }

    // epilogue: ctx[b][s][h*64 + col]
    const int b = z >> 4, h = z & (NHEAD - 1);
#pragma unroll
    for (int i = 0; i < 2; i++) {
        int r0 = m0 + warp_m * 32 + i * 16 + g;
        int r1 = r0 + 8;
#pragma unroll
        for (int j = 0; j < 4; j++) {
            int col = warp_n * 32 + j * 8 + tig * 2;
            *(float2*)(ctx + ((size_t)b * SEQ + r0) * DMODEL + h * HDIM + col) =
                make_float2(acc[i][j][0], acc[i][j][1]);
            *(float2*)(ctx + ((size_t)b * SEQ + r1) * DMODEL + h * HDIM + col) =
                make_float2(acc[i][j][2], acc[i][j][3]);
        }
    }
}

// ===================== transpose (Wq, Wfc) ==================================
__global__ __launch_bounds__(256) void transpose_kernel(
    const float* __restrict__ in, float* __restrict__ out)
{
    __shared__ float tile[32][33];
    int x0 = blockIdx.x * 32, y0 = blockIdx.y * 32;
    for (int i = threadIdx.y; i < 32; i += 8)
        tile[i][threadIdx.x] = in[(size_t)(y0 + i) * DMODEL + x0 + threadIdx.x];
    __syncthreads();
    for (int i = threadIdx.y; i < 32; i += 8)
        out[(size_t)(x0 + i) * DMODEL + y0 + threadIdx.x] = tile[threadIdx.x][i];
}

// ===================== layernorm ============================================
__device__ __forceinline__ float warpSum(float v) {
#pragma unroll
    for (int o = 16; o > 0; o >>= 1) v += __shfl_xor_sync(0xffffffffu, v, o);
    return v;
}

__global__ __launch_bounds__(256) void ln_kernel(
    const float* __restrict__ q, const float* __restrict__ fc,
    const float* __restrict__ gamma, const float* __restrict__ beta,
    float* __restrict__ out)
{
    const size_t base = (size_t)blockIdx.x * DMODEL;
    const int tid = threadIdx.x;
    const int lane = tid & 31, wid = tid >> 5;
    __shared__ float shs[8];
    __shared__ float shq[8];

    float4 xq = *(const float4*)(q + base + tid * 4);
    float4 xf = *(const float4*)(fc + base + tid * 4);
    float x0 = xq.x + xf.x, x1 = xq.y + xf.y, x2 = xq.z + xf.z, x3 = xq.w + xf.w;

    float s  = x0 + x1 + x2 + x3;
    float sq = x0 * x0 + x1 * x1 + x2 * x2 + x3 * x3;
    s = warpSum(s);
    sq = warpSum(sq);
    if (!lane) { shs[wid] = s; shq[wid] = sq; }
    __syncthreads();
    if (tid < 32) {
        float ts = (tid < 8) ? shs[tid] : 0.f;
        float tq = (tid < 8) ? shq[tid] : 0.f;
        ts = warpSum(ts);
        tq = warpSum(tq);
        if (!tid) { shs[0] = ts; shq[0] = tq; }
    }
    __syncthreads();

    const float inv_n = 1.f / DMODEL;
    float mu  = shs[0] * inv_n;
    float var = shq[0] * inv_n - mu * mu;
    float r = rsqrtf(var + 1e-6f);

    float4 gg = *(const float4*)(gamma + tid * 4);
    float4 be = *(const float4*)(beta + tid * 4);
    float4 y;
    y.x = (x0 - mu) * r * gg.x + be.x;
    y.y = (x1 - mu) * r * gg.y + be.y;
    y.z = (x2 - mu) * r * gg.z + be.z;
    y.w = (x3 - mu) * r * gg.w + be.w;
    *(float4*)(out + base + tid * 4) = y;
}

// ===================== launch ===============================================
extern "C" void kernel_launch(void* const* d_in, const int* in_sizes, int n_in,
                              void* d_out, int out_size)
{
    const float* q     = (const float*)d_in[0];
    const float* k     = (const float*)d_in[1];
    const float* v     = (const float*)d_in[2];
    const float* Wq    = (const float*)d_in[3];
    const float* bq    = (const float*)d_in[4];
    const float* Wfc   = (const float*)d_in[5];
    const float* bfc   = (const float*)d_in[6];
    const float* gamma = (const float*)d_in[7];
    const float* beta  = (const float*)d_in[8];

    float* out      = (float*)d_out;
    float* x_out    = out;
    float* attn_out = out + PROJ_ELEMS;

    float* base = nullptr;
    cudaGetSymbolAddress((void**)&base, g_scratch);
    float* qh     = base;
    float* kh     = base + PROJ_ELEMS;
    float* vhT    = base + 2 * PROJ_ELEMS;   // [B,H,DK,S]
    float* ctx    = base + 3 * PROJ_ELEMS;
    float* fcb    = base + 4 * PROJ_ELEMS;
    float* WqT    = base + 5 * PROJ_ELEMS;
    float* WfcT   = WqT + 1024 * 1024;
    float* mstats = WfcT + 1024 * 1024;
    float* lstats = mstats + NROWS * NTILES;
    float* corr   = lstats + NROWS * NTILES;

    dim3 blk(256);

    transpose_kernel<<<dim3(32, 32), dim3(32, 8)>>>(Wq, WqT);
    transpose_kernel<<<dim3(32, 32), dim3(32, 8)>>>(Wfc, WfcT);

    // Projections
    dim3 gproj(DMODEL / 128, NTOK / 128, 1);
    tc_gemm<128, EPI_PROJ ><<<gproj, blk>>>(q, WqT, bq, qh,  DMODEL, DMODEL, DMODEL);
    tc_gemm<128, EPI_PROJ ><<<gproj, blk>>>(k, WqT, bq, kh,  DMODEL, DMODEL, DMODEL);
    tc_gemm<128, EPI_PROJV><<<gproj, blk>>>(v, WqT, bq, vhT, DMODEL, DMODEL, DMODEL);

    // Scores + tile softmax stats -> P~ in attn region
    dim3 gsc(SEQ / 128, SEQ / 128, NBH);
    scores_kernel<<<gsc, blk>>>(qh, kh, attn_out, mstats, lstats);

    // Row-global correction factors
    combine_kernel<<<(unsigned)(NROWS / 256), blk>>>(mstats, lstats, corr);

    // Fused normalize + ctx GEMM (writes final attn + ctx)
    dim3 gctx(SEQ / 128, NBH);
    ctx_fused_kernel<<<gctx, blk>>>(vhT, corr, attn_out, ctx);

    // Out projection
    dim3 gfc(DMODEL / 128, NTOK / 128, 1);
    tc_gemm<128, EPI_PLAIN><<<gfc, blk>>>(ctx, WfcT, bfc, fcb,
                                          DMODEL, DMODEL, DMODEL);

    ln_kernel<<<NTOK, blk>>>(q, fcb, gamma, beta, x_out);
}

// round 10
// speedup vs baseline: 1.0058x; 1.0058x over previous
#include <cuda_runtime.h>
#include <stdint.h>
#include <math.h>

#define BATCH  4
#define SEQ    2048
#define DMODEL 1024
#define NHEAD  16
#define HDIM   64
#define NBH    (BATCH * NHEAD)        // 64
#define NTOK   (BATCH * SEQ)          // 8192
#define PROJ_ELEMS ((size_t)NTOK * DMODEL)  // 8388608

// qh, kh, vhT, ctx, fcb (each PROJ_ELEMS) + WqT + WfcT (1M each)
__device__ float g_scratch[5 * PROJ_ELEMS + 2 * 1024 * 1024];

// ===================== helpers ==============================================
__device__ __forceinline__ uint32_t smem_u32(const void* p) {
    uint32_t a;
    asm("{ .reg .u64 t; cvta.to.shared.u64 t, %1; cvt.u32.u64 %0, t; }"
        : "=r"(a) : "l"(p));
    return a;
}
__device__ __forceinline__ void cp16(void* s, const void* g) {
    asm volatile("cp.async.cg.shared.global [%0], [%1], 16;"
                 :: "r"(smem_u32(s)), "l"(g));
}
__device__ __forceinline__ void cp_commit() {
    asm volatile("cp.async.commit_group;");
}
template <int N>
__device__ __forceinline__ void cp_wait() {
    asm volatile("cp.async.wait_group %0;" :: "n"(N));
}
__device__ __forceinline__ uint32_t f2tf(float x) {
    uint32_t r;
    asm("cvt.rn.tf32.f32 %0, %1;" : "=r"(r) : "f"(x));
    return r;
}
__device__ __forceinline__ float rnd(float x) {   // tf32-rounded fp32 value
    return __uint_as_float(f2tf(x));
}
__device__ __forceinline__ void mma_tf32(float* d, const uint32_t* a,
                                         const uint32_t* b) {
    asm volatile(
        "mma.sync.aligned.m16n8k8.row.col.f32.tf32.tf32.f32 "
        "{%0,%1,%2,%3}, {%4,%5,%6,%7}, {%8,%9}, {%0,%1,%2,%3};"
        : "+f"(d[0]), "+f"(d[1]), "+f"(d[2]), "+f"(d[3])
        : "r"(a[0]), "r"(a[1]), "r"(a[2]), "r"(a[3]), "r"(b[0]), "r"(b[1]));
}
__device__ __forceinline__ void ldsm4(uint32_t* r, uint32_t addr) {
    asm volatile("ldmatrix.sync.aligned.m8n8.x4.shared.b16 {%0,%1,%2,%3}, [%4];"
                 : "=r"(r[0]), "=r"(r[1]), "=r"(r[2]), "=r"(r[3]) : "r"(addr));
}

// ===================== unified tf32 mma GEMM ================================
// D[m][n] = sum_k A[m][k] * B[n][k]   (A:[M,K] lda, B:[N,K] ldb, K-major)
// SMEM tiles hold tf32-pre-rounded values; fragments loaded via ldmatrix.
// ARAW: A in gmem is raw fp32 -> staged via LDG+cvt+STS (register prefetch);
//       otherwise A pre-rounded -> cp.async.  B always pre-rounded -> cp.async.
enum { EPI_PROJ = 0, EPI_PROJV = 1, EPI_SCORES = 2, EPI_CTX = 3, EPI_PLAIN = 4 };

template <int BN, int EPI, bool ARAW>
__global__ __launch_bounds__(256, 2) void tc_gemm(
    const float* __restrict__ A, const float* __restrict__ B,
    const float* __restrict__ bias, float* __restrict__ C,
    int K, int lda, int ldb)
{
    constexpr int BM = 128, BK = 16, LDS_ = 20;
    constexpr int WARPS_M = (BN == 128) ? 2 : 4;
    constexpr int WARPS_N = 8 / WARPS_M;
    constexpr int WM = BM / WARPS_M, WN = BN / WARPS_N;   // 64x32 | 32x32
    constexpr int MT = WM / 16, NT = WN / 8;              // 4x4   | 2x4
    constexpr int ASTR = BM * LDS_;
    constexpr int BSTR = BN * LDS_;

    __shared__ __align__(16) float As[2][ASTR];
    __shared__ __align__(16) float Bs[2][BSTR];

    const int tid  = threadIdx.x;
    const int warp = tid >> 5;
    const int lane = tid & 31;
    const int g    = lane >> 2;
    const int tig  = lane & 3;
    const int warp_m = warp / WARPS_N;
    const int warp_n = warp % WARPS_N;
    const int m0 = blockIdx.y * BM;
    const int n0 = blockIdx.x * BN;
    const int z  = blockIdx.z;

    const float* Ag = A;
    const float* Bg = B;
    if (EPI == EPI_SCORES) { Ag += (size_t)z * SEQ * HDIM; Bg += (size_t)z * SEQ * HDIM; }
    if (EPI == EPI_CTX)    { Ag += (size_t)z * SEQ * SEQ;  Bg += (size_t)z * HDIM * SEQ; }

    const int lr  = tid >> 2;        // 0..63
    const int lc4 = tid & 3;

    // ldmatrix per-lane addresses (stage 0, kt 0)
    const uint32_t a_base = smem_u32(&As[0][0]);
    const uint32_t b_base = smem_u32(&Bs[0][0]);
    uint32_t aaddr[MT], baddr[NT / 2];
#pragma unroll
    for (int i = 0; i < MT; i++)
        aaddr[i] = a_base +
            (((warp_m * WM + i * 16 + (lane & 15)) * LDS_) + ((lane >> 4) << 2)) * 4;
#pragma unroll
    for (int jj = 0; jj < NT / 2; jj++)
        baddr[jj] = b_base +
            (((warp_n * WN + jj * 16 + (lane & 15)) * LDS_) + ((lane >> 4) << 2)) * 4;

    float acc[MT][NT][4];
#pragma unroll
    for (int i = 0; i < MT; i++)
#pragma unroll
        for (int j = 0; j < NT; j++)
#pragma unroll
            for (int r = 0; r < 4; r++) acc[i][j][r] = 0.f;

    const int nit = K / BK;
    float4 ar0, ar1;

    auto ldgA = [&](int k0) {
        ar0 = *(const float4*)(Ag + (size_t)(m0 + lr) * lda + k0 + lc4 * 4);
        ar1 = *(const float4*)(Ag + (size_t)(m0 + lr + 64) * lda + k0 + lc4 * 4);
    };
    auto stsA = [&](int s) {
        uint32_t ad0 = smem_u32(&As[s][lr * LDS_ + lc4 * 4]);
        asm volatile("st.shared.v4.b32 [%0], {%1,%2,%3,%4};" :: "r"(ad0),
            "r"(f2tf(ar0.x)), "r"(f2tf(ar0.y)), "r"(f2tf(ar0.z)), "r"(f2tf(ar0.w)));
        uint32_t ad1 = smem_u32(&As[s][(lr + 64) * LDS_ + lc4 * 4]);
        asm volatile("st.shared.v4.b32 [%0], {%1,%2,%3,%4};" :: "r"(ad1),
            "r"(f2tf(ar1.x)), "r"(f2tf(ar1.y)), "r"(f2tf(ar1.z)), "r"(f2tf(ar1.w)));
    };
    auto cpA = [&](int s, int k0) {
        cp16(&As[s][lr * LDS_ + lc4 * 4],
             Ag + (size_t)(m0 + lr) * lda + k0 + lc4 * 4);
        cp16(&As[s][(lr + 64) * LDS_ + lc4 * 4],
             Ag + (size_t)(m0 + lr + 64) * lda + k0 + lc4 * 4);
    };
    auto cpB = [&](int s, int k0) {
        cp16(&Bs[s][lr * LDS_ + lc4 * 4],
             Bg + (size_t)(n0 + lr) * ldb + k0 + lc4 * 4);
        if (BN == 128)
            cp16(&Bs[s][(lr + 64) * LDS_ + lc4 * 4],
                 Bg + (size_t)(n0 + lr + 64) * ldb + k0 + lc4 * 4);
    };

    if (ARAW) { ldgA(0); stsA(0); } else { cpA(0, 0); }
    cpB(0, 0);
    cp_commit();

    for (int it = 0; it < nit; it++) {
        const int s = it & 1;
        if (it + 1 < nit) {
            if (ARAW) ldgA((it + 1) * BK);
            else      cpA(s ^ 1, (it + 1) * BK);
            cpB(s ^ 1, (it + 1) * BK);
            cp_commit();
            cp_wait<1>();
        } else {
            cp_wait<0>();
        }
        __syncthreads();

        const uint32_t ao = s ? ASTR * 4 : 0;
        const uint32_t bo = s ? BSTR * 4 : 0;
#pragma unroll
        for (int kt = 0; kt < 2; kt++) {
            uint32_t af[MT][4];
#pragma unroll
            for (int i = 0; i < MT; i++)
                ldsm4(af[i], aaddr[i] + ao + kt * 32);
            uint32_t bf[NT][2];
#pragma unroll
            for (int jj = 0; jj < NT / 2; jj++) {
                uint32_t t[4];
                ldsm4(t, baddr[jj] + bo + kt * 32);
                bf[2 * jj][0]     = t[0];
                bf[2 * jj + 1][0] = t[1];
                bf[2 * jj][1]     = t[2];
                bf[2 * jj + 1][1] = t[3];
            }
#pragma unroll
            for (int i = 0; i < MT; i++)
#pragma unroll
                for (int j = 0; j < NT; j++)
                    mma_tf32(acc[i][j], af[i], bf[j]);
        }
        __syncthreads();
        if (ARAW && it + 1 < nit) stsA(s ^ 1);
    }

    // ---------------- epilogue ----------------------------------------------
#pragma unroll
    for (int i = 0; i < MT; i++) {
        int r0 = m0 + warp_m * WM + i * 16 + g;
        int r1 = r0 + 8;
#pragma unroll
        for (int j = 0; j < NT; j++) {
            int c = n0 + warp_n * WN + j * 8 + tig * 2;
            float d0 = acc[i][j][0], d1 = acc[i][j][1];
            float d2 = acc[i][j][2], d3 = acc[i][j][3];

            if (EPI == EPI_SCORES) {
                float* base = C + (size_t)z * SEQ * SEQ + c;
                *(float2*)(base + (size_t)r0 * SEQ) =
                    make_float2(d0 * 0.125f, d1 * 0.125f);
                *(float2*)(base + (size_t)r1 * SEQ) =
                    make_float2(d2 * 0.125f, d3 * 0.125f);
            } else if (EPI == EPI_PLAIN) {
                float2 bb = *(const float2*)(bias + c);
                *(float2*)(C + (size_t)r0 * DMODEL + c) =
                    make_float2(d0 + bb.x, d1 + bb.y);
                *(float2*)(C + (size_t)r1 * DMODEL + c) =
                    make_float2(d2 + bb.x, d3 + bb.y);
            } else if (EPI == EPI_PROJ) {
                float2 bb = *(const float2*)(bias + c);
                int h = c >> 6, dd = c & 63;
                {
                    int b = r0 >> 11, ss = r0 & (SEQ - 1);
                    *(float2*)(C + ((((size_t)b * NHEAD + h) * SEQ + ss) << 6) + dd) =
                        make_float2(rnd(d0 + bb.x), rnd(d1 + bb.y));
                }
                {
                    int b = r1 >> 11, ss = r1 & (SEQ - 1);
                    *(float2*)(C + ((((size_t)b * NHEAD + h) * SEQ + ss) << 6) + dd) =
                        make_float2(rnd(d2 + bb.x), rnd(d3 + bb.y));
                }
            } else if (EPI == EPI_PROJV) {
                float2 bb = *(const float2*)(bias + c);
                int h = c >> 6, dd = c & 63;
                {
                    int b = r0 >> 11, ss = r0 & (SEQ - 1);
                    float* base = C + (((size_t)b * NHEAD + h) * HDIM + dd) * SEQ + ss;
                    base[0]   = rnd(d0 + bb.x);
                    base[SEQ] = rnd(d1 + bb.y);
                }
                {
                    int b = r1 >> 11, ss = r1 & (SEQ - 1);
                    float* base = C + (((size_t)b * NHEAD + h) * HDIM + dd) * SEQ + ss;
                    base[0]   = rnd(d2 + bb.x);
                    base[SEQ] = rnd(d3 + bb.y);
                }
            } else {  // EPI_CTX: ctx[b][s][h*64 + c], tf32-pre-rounded
                int b = z >> 4, h = z & (NHEAD - 1);
                *(float2*)(C + ((size_t)b * SEQ + r0) * DMODEL + h * HDIM + c) =
                    make_float2(rnd(d0), rnd(d1));
                *(float2*)(C + ((size_t)b * SEQ + r1) * DMODEL + h * HDIM + c) =
                    make_float2(rnd(d2), rnd(d3));
            }
        }
    }
}

// ===================== transpose + tf32 round (Wq, Wfc) =====================
__global__ __launch_bounds__(256) void transpose_kernel(
    const float* __restrict__ in, float* __restrict__ out)
{
    __shared__ float tile[32][33];
    int x0 = blockIdx.x * 32, y0 = blockIdx.y * 32;
    for (int i = threadIdx.y; i < 32; i += 8)
        tile[i][threadIdx.x] = in[(size_t)(y0 + i) * DMODEL + x0 + threadIdx.x];
    __syncthreads();
    for (int i = threadIdx.y; i < 32; i += 8)
        out[(size_t)(x0 + i) * DMODEL + y0 + threadIdx.x] =
            rnd(tile[threadIdx.x][i]);
}

// ===================== softmax / layernorm ==================================
__device__ __forceinline__ float warpMax(float v) {
#pragma unroll
    for (int o = 16; o > 0; o >>= 1) v = fmaxf(v, __shfl_xor_sync(0xffffffffu, v, o));
    return v;
}
__device__ __forceinline__ float warpSum(float v) {
#pragma unroll
    for (int o = 16; o > 0; o >>= 1) v += __shfl_xor_sync(0xffffffffu, v, o);
    return v;
}

__global__ __launch_bounds__(256) void softmax_kernel(float* __restrict__ attn)
{
    float* p = attn + (size_t)blockIdx.x * SEQ;
    const int tid = threadIdx.x;
    const int lane = tid & 31, wid = tid >> 5;
    __shared__ float sh[8];

    float4 a = *(float4*)(p + tid * 4);
    float4 b = *(float4*)(p + 1024 + tid * 4);

    float m = fmaxf(fmaxf(fmaxf(a.x, a.y), fmaxf(a.z, a.w)),
                    fmaxf(fmaxf(b.x, b.y), fmaxf(b.z, b.w)));
    m = warpMax(m);
    if (!lane) sh[wid] = m;
    __syncthreads();
    if (tid < 32) {
        float t = (tid < 8) ? sh[tid] : -3.4e38f;
        t = warpMax(t);
        if (!tid) sh[0] = t;
    }
    __syncthreads();
    m = sh[0];
    __syncthreads();

    a.x = __expf(a.x - m); a.y = __expf(a.y - m);
    a.z = __expf(a.z - m); a.w = __expf(a.w - m);
    b.x = __expf(b.x - m); b.y = __expf(b.y - m);
    b.z = __expf(b.z - m); b.w = __expf(b.w - m);

    float s = (a.x + a.y + a.z + a.w) + (b.x + b.y + b.z + b.w);
    s = warpSum(s);
    if (!lane) sh[wid] = s;
    __syncthreads();
    if (tid < 32) {
        float t = (tid < 8) ? sh[tid] : 0.f;
        t = warpSum(t);
        if (!tid) sh[0] = t;
    }
    __syncthreads();
    float inv = 1.f / sh[0];

    a.x *= inv; a.y *= inv; a.z *= inv; a.w *= inv;
    b.x *= inv; b.y *= inv; b.z *= inv; b.w *= inv;
    *(float4*)(p + tid * 4) = a;
    *(float4*)(p + 1024 + tid * 4) = b;
}

__global__ __launch_bounds__(256) void ln_kernel(
    const float* __restrict__ q, const float* __restrict__ fc,
    const float* __restrict__ gamma, const float* __restrict__ beta,
    float* __restrict__ out)
{
    const size_t base = (size_t)blockIdx.x * DMODEL;
    const int tid = threadIdx.x;
    const int lane = tid & 31, wid = tid >> 5;
    __shared__ float shs[8];
    __shared__ float shq[8];

    float4 xq = *(const float4*)(q + base + tid * 4);
    float4 xf = *(const float4*)(fc + base + tid * 4);
    float x0 = xq.x + xf.x, x1 = xq.y + xf.y, x2 = xq.z + xf.z, x3 = xq.w + xf.w;

    float s  = x0 + x1 + x2 + x3;
    float sq = x0 * x0 + x1 * x1 + x2 * x2 + x3 * x3;
    s = warpSum(s);
    sq = warpSum(sq);
    if (!lane) { shs[wid] = s; shq[wid] = sq; }
    __syncthreads();
    if (tid < 32) {
        float ts = (tid < 8) ? shs[tid] : 0.f;
        float tq = (tid < 8) ? shq[tid] : 0.f;
        ts = warpSum(ts);
        tq = warpSum(tq);
        if (!tid) { shs[0] = ts; shq[0] = tq; }
    }
    __syncthreads();

    const float inv_n = 1.f / DMODEL;
    float mu  = shs[0] * inv_n;
    float var = shq[0] * inv_n - mu * mu;
    float r = rsqrtf(var + 1e-6f);

    float4 gg = *(const float4*)(gamma + tid * 4);
    float4 be = *(const float4*)(beta + tid * 4);
    float4 y;
    y.x = (x0 - mu) * r * gg.x + be.x;
    y.y = (x1 - mu) * r * gg.y + be.y;
    y.z = (x2 - mu) * r * gg.z + be.z;
    y.w = (x3 - mu) * r * gg.w + be.w;
    *(float4*)(out + base + tid * 4) = y;
}

// ===================== launch ===============================================
extern "C" void kernel_launch(void* const* d_in, const int* in_sizes, int n_in,
                              void* d_out, int out_size)
{
    const float* q     = (const float*)d_in[0];
    const float* k     = (const float*)d_in[1];
    const float* v     = (const float*)d_in[2];
    const float* Wq    = (const float*)d_in[3];
    const float* bq    = (const float*)d_in[4];
    const float* Wfc   = (const float*)d_in[5];
    const float* bfc   = (const float*)d_in[6];
    const float* gamma = (const float*)d_in[7];
    const float* beta  = (const float*)d_in[8];

    float* out      = (float*)d_out;
    float* x_out    = out;
    float* attn_out = out + PROJ_ELEMS;

    float* base = nullptr;
    cudaGetSymbolAddress((void**)&base, g_scratch);
    float* qh   = base;
    float* kh   = base + PROJ_ELEMS;
    float* vhT  = base + 2 * PROJ_ELEMS;   // [B,H,DK,S]
    float* ctx  = base + 3 * PROJ_ELEMS;
    float* fcb  = base + 4 * PROJ_ELEMS;
    float* WqT  = base + 5 * PROJ_ELEMS;
    float* WfcT = WqT + 1024 * 1024;

    dim3 blk(256);

    transpose_kernel<<<dim3(32, 32), dim3(32, 8)>>>(Wq, WqT);
    transpose_kernel<<<dim3(32, 32), dim3(32, 8)>>>(Wfc, WfcT);

    // Projections (A raw fp32, B pre-rounded)
    dim3 gproj(DMODEL / 128, NTOK / 128, 1);
    tc_gemm<128, EPI_PROJ,  true><<<gproj, blk>>>(q, WqT, bq, qh,  DMODEL, DMODEL, DMODEL);
    tc_gemm<128, EPI_PROJ,  true><<<gproj, blk>>>(k, WqT, bq, kh,  DMODEL, DMODEL, DMODEL);
    tc_gemm<128, EPI_PROJV, true><<<gproj, blk>>>(v, WqT, bq, vhT, DMODEL, DMODEL, DMODEL);

    // Scores (both operands pre-rounded)
    dim3 gsc(SEQ / 128, SEQ / 128, NBH);
    tc_gemm<128, EPI_SCORES, false><<<gsc, blk>>>(qh, kh, nullptr, attn_out,
                                                  HDIM, HDIM, HDIM);

    softmax_kernel<<<NBH * SEQ, blk>>>(attn_out);

    // ctx (A = attn raw fp32, B = vhT pre-rounded)
    dim3 gctx(1, SEQ / 128, NBH);
    tc_gemm<64, EPI_CTX, true><<<gctx, blk>>>(attn_out, vhT, nullptr, ctx,
                                              SEQ, SEQ, SEQ);

    // Out projection (ctx pre-rounded)
    dim3 gfc(DMODEL / 128, NTOK / 128, 1);
    tc_gemm<128, EPI_PLAIN, false><<<gfc, blk>>>(ctx, WfcT, bfc, fcb,
                                                 DMODEL, DMODEL, DMODEL);

    ln_kernel<<<NTOK, blk>>>(q, fcb, gamma, beta, x_out);
}

// round 14
// speedup vs baseline: 1.3532x; 1.3454x over previous
#include <cuda_runtime.h>
#include <cuda_fp16.h>
#include <stdint.h>
#include <math.h>

#define BATCH  4
#define SEQ    2048
#define DMODEL 1024
#define NHEAD  16
#define HDIM   64
#define NBH    (BATCH * NHEAD)        // 64
#define NTOK   (BATCH * SEQ)          // 8192
#define PROJ_ELEMS ((size_t)NTOK * DMODEL)  // 8388608

// Layout (in floats): qh_h, kh_h, vhT_h, ctx_h (each PROJ_ELEMS/2 floats as halves),
// fcb (PROJ_ELEMS floats), WqT_h, WfcT_h (512K floats each as halves)
__device__ float g_scratch[4 * (PROJ_ELEMS / 2) + PROJ_ELEMS + 2 * 512 * 1024];

// ===================== helpers ==============================================
__device__ __forceinline__ uint32_t smem_u32(const void* p) {
    uint32_t a;
    asm("{ .reg .u64 t; cvta.to.shared.u64 t, %1; cvt.u32.u64 %0, t; }"
        : "=r"(a) : "l"(p));
    return a;
}
__device__ __forceinline__ void cp16(void* s, const void* g) {
    asm volatile("cp.async.cg.shared.global [%0], [%1], 16;"
                 :: "r"(smem_u32(s)), "l"(g));
}
__device__ __forceinline__ void cp_commit() {
    asm volatile("cp.async.commit_group;");
}
template <int N>
__device__ __forceinline__ void cp_wait() {
    asm volatile("cp.async.wait_group %0;" :: "n"(N));
}
__device__ __forceinline__ uint32_t pack_h2(float x, float y) {
    __half2 h = __float22half2_rn(make_float2(x, y));
    return *(uint32_t*)&h;
}
__device__ __forceinline__ void mma_f16(float* d, const uint32_t* a,
                                        const uint32_t* b) {
    asm volatile(
        "mma.sync.aligned.m16n8k16.row.col.f32.f16.f16.f32 "
        "{%0,%1,%2,%3}, {%4,%5,%6,%7}, {%8,%9}, {%0,%1,%2,%3};"
        : "+f"(d[0]), "+f"(d[1]), "+f"(d[2]), "+f"(d[3])
        : "r"(a[0]), "r"(a[1]), "r"(a[2]), "r"(a[3]), "r"(b[0]), "r"(b[1]));
}
__device__ __forceinline__ void ldsm4(uint32_t* r, uint32_t addr) {
    asm volatile("ldmatrix.sync.aligned.m8n8.x4.shared.b16 {%0,%1,%2,%3}, [%4];"
                 : "=r"(r[0]), "=r"(r[1]), "=r"(r[2]), "=r"(r[3]) : "r"(addr));
}

// ===================== unified fp16 mma GEMM ================================
// D[m][n] = sum_k A[m][k] * B[n][k]   (K-major operands)
// B always pre-rounded fp16 in gmem (cp.async).  ARAW: A is raw fp32 in gmem
// -> staged LDG float4 + cvt-rn + STS half; else A is fp16 -> cp.async.
enum { EPI_PROJ = 0, EPI_PROJV = 1, EPI_SCORES = 2, EPI_CTX = 3, EPI_PLAIN = 4 };

template <int BN, int EPI, bool ARAW>
__global__ __launch_bounds__(256, 2) void tc_gemm(
    const void* __restrict__ Av, const __half* __restrict__ B,
    const float* __restrict__ bias, void* __restrict__ Cv,
    int K, int lda, int ldb)
{
    constexpr int BM = 128, BK = 32, LDSH = 40;       // halves per smem row
    constexpr int WARPS_M = (BN == 128) ? 2 : 4;
    constexpr int WARPS_N = 8 / WARPS_M;
    constexpr int WM = BM / WARPS_M, WN = BN / WARPS_N;   // 64x32 | 32x32
    constexpr int MT = WM / 16, NT = WN / 8;              // 4x4   | 2x4
    constexpr int ASTRH = BM * LDSH;
    constexpr int BSTRH = BN * LDSH;

    __shared__ __align__(16) __half As[2][ASTRH];
    __shared__ __align__(16) __half Bs[2][BSTRH];

    const int tid  = threadIdx.x;
    const int warp = tid >> 5;
    const int lane = tid & 31;
    const int g    = lane >> 2;
    const int tig  = lane & 3;
    const int warp_m = warp / WARPS_N;
    const int warp_n = warp % WARPS_N;
    const int m0 = blockIdx.y * BM;
    const int n0 = blockIdx.x * BN;
    const int z  = blockIdx.z;

    const float*  Agf = (const float*)Av;
    const __half* Agh = (const __half*)Av;
    const __half* Bg  = B;
    if (EPI == EPI_SCORES) { Agh += (size_t)z * SEQ * HDIM; Bg += (size_t)z * SEQ * HDIM; }
    if (EPI == EPI_CTX)    { Agf += (size_t)z * SEQ * SEQ;  Bg += (size_t)z * HDIM * SEQ; }

    const int lr  = tid >> 2;        // 0..63
    const int lc4 = tid & 3;         // 16B chunk (8 halves) within BK=32

    // ldmatrix per-lane addresses (stage 0, kt 0): row = lane&15, chunk = lane>>4
    const uint32_t a_base = smem_u32(&As[0][0]);
    const uint32_t b_base = smem_u32(&Bs[0][0]);
    uint32_t aaddr[MT], baddr[NT / 2];
#pragma unroll
    for (int i = 0; i < MT; i++)
        aaddr[i] = a_base +
            (((warp_m * WM + i * 16 + (lane & 15)) * LDSH) + ((lane >> 4) << 3)) * 2;
#pragma unroll
    for (int jj = 0; jj < NT / 2; jj++)
        baddr[jj] = b_base +
            (((warp_n * WN + jj * 16 + (lane & 15)) * LDSH) + ((lane >> 4) << 3)) * 2;

    float acc[MT][NT][4];
#pragma unroll
    for (int i = 0; i < MT; i++)
#pragma unroll
        for (int j = 0; j < NT; j++)
#pragma unroll
            for (int r = 0; r < 4; r++) acc[i][j][r] = 0.f;

    const int nit = K / BK;

    // ARAW staging: thread t covers row rr, float4 slots q4..q4+3 (8 slots/row)
    const int rr = tid >> 1;
    const int q4 = (tid & 1) * 4;
    float4 ar[4];

    auto ldgA = [&](int k0) {
#pragma unroll
        for (int i = 0; i < 4; i++)
            ar[i] = *(const float4*)(Agf + (size_t)(m0 + rr) * lda + k0 + (q4 + i) * 4);
    };
    auto stsA = [&](int s) {
#pragma unroll
        for (int i = 0; i < 4; i++) {
            uint32_t h0 = pack_h2(ar[i].x, ar[i].y);
            uint32_t h1 = pack_h2(ar[i].z, ar[i].w);
            uint32_t ad = smem_u32(&As[s][rr * LDSH + (q4 + i) * 4]);
            asm volatile("st.shared.v2.b32 [%0], {%1,%2};" :: "r"(ad), "r"(h0), "r"(h1));
        }
    };
    auto cpA = [&](int s, int k0) {
        cp16(&As[s][lr * LDSH + lc4 * 8],
             Agh + (size_t)(m0 + lr) * lda + k0 + lc4 * 8);
        cp16(&As[s][(lr + 64) * LDSH + lc4 * 8],
             Agh + (size_t)(m0 + lr + 64) * lda + k0 + lc4 * 8);
    };
    auto cpB = [&](int s, int k0) {
        cp16(&Bs[s][lr * LDSH + lc4 * 8],
             Bg + (size_t)(n0 + lr) * ldb + k0 + lc4 * 8);
        if (BN == 128)
            cp16(&Bs[s][(lr + 64) * LDSH + lc4 * 8],
                 Bg + (size_t)(n0 + lr + 64) * ldb + k0 + lc4 * 8);
    };

    if (ARAW) { ldgA(0); stsA(0); } else { cpA(0, 0); }
    cpB(0, 0);
    cp_commit();

    for (int it = 0; it < nit; it++) {
        const int s = it & 1;
        if (it + 1 < nit) {
            if (ARAW) ldgA((it + 1) * BK);
            else      cpA(s ^ 1, (it + 1) * BK);
            cpB(s ^ 1, (it + 1) * BK);
            cp_commit();
            cp_wait<1>();
        } else {
            cp_wait<0>();
        }
        __syncthreads();

        const uint32_t ao = s ? ASTRH * 2 : 0;
        const uint32_t bo = s ? BSTRH * 2 : 0;
#pragma unroll
        for (int kt = 0; kt < 2; kt++) {          // k16 per step
            uint32_t af[MT][4];
#pragma unroll
            for (int i = 0; i < MT; i++)
                ldsm4(af[i], aaddr[i] + ao + kt * 32);   // +16 halves
            uint32_t bf[NT][2];
#pragma unroll
            for (int jj = 0; jj < NT / 2; jj++) {
                uint32_t t[4];
                ldsm4(t, baddr[jj] + bo + kt * 32);
                bf[2 * jj][0]     = t[0];
                bf[2 * jj + 1][0] = t[1];
                bf[2 * jj][1]     = t[2];
                bf[2 * jj + 1][1] = t[3];
            }
#pragma unroll
            for (int i = 0; i < MT; i++)
#pragma unroll
                for (int j = 0; j < NT; j++)
                    mma_f16(acc[i][j], af[i], bf[j]);
        }
        __syncthreads();
        if (ARAW && it + 1 < nit) stsA(s ^ 1);
    }

    // ---------------- epilogue ----------------------------------------------
#pragma unroll
    for (int i = 0; i < MT; i++) {
        int r0 = m0 + warp_m * WM + i * 16 + g;
        int r1 = r0 + 8;
#pragma unroll
        for (int j = 0; j < NT; j++) {
            int c = n0 + warp_n * WN + j * 8 + tig * 2;
            float d0 = acc[i][j][0], d1 = acc[i][j][1];
            float d2 = acc[i][j][2], d3 = acc[i][j][3];

            if (EPI == EPI_SCORES) {
                float* Cf = (float*)Cv + (size_t)z * SEQ * SEQ + c;
                *(float2*)(Cf + (size_t)r0 * SEQ) =
                    make_float2(d0 * 0.125f, d1 * 0.125f);
                *(float2*)(Cf + (size_t)r1 * SEQ) =
                    make_float2(d2 * 0.125f, d3 * 0.125f);
            } else if (EPI == EPI_PLAIN) {
                float* Cf = (float*)Cv;
                float2 bb = *(const float2*)(bias + c);
                *(float2*)(Cf + (size_t)r0 * DMODEL + c) =
                    make_float2(d0 + bb.x, d1 + bb.y);
                *(float2*)(Cf + (size_t)r1 * DMODEL + c) =
                    make_float2(d2 + bb.x, d3 + bb.y);
            } else if (EPI == EPI_PROJ) {
                __half* Ch = (__half*)Cv;
                float2 bb = *(const float2*)(bias + c);
                int h = c >> 6, dd = c & 63;
                {
                    int b = r0 >> 11, ss = r0 & (SEQ - 1);
                    *(uint32_t*)(Ch + ((((size_t)b * NHEAD + h) * SEQ + ss) << 6) + dd) =
                        pack_h2(d0 + bb.x, d1 + bb.y);
                }
                {
                    int b = r1 >> 11, ss = r1 & (SEQ - 1);
                    *(uint32_t*)(Ch + ((((size_t)b * NHEAD + h) * SEQ + ss) << 6) + dd) =
                        pack_h2(d2 + bb.x, d3 + bb.y);
                }
            } else if (EPI == EPI_PROJV) {
                __half* Ch = (__half*)Cv;
                float2 bb = *(const float2*)(bias + c);
                int h = c >> 6, dd = c & 63;
                {
                    int b = r0 >> 11, ss = r0 & (SEQ - 1);
                    __half* base = Ch + (((size_t)b * NHEAD + h) * HDIM + dd) * SEQ + ss;
                    base[0]   = __float2half_rn(d0 + bb.x);
                    base[SEQ] = __float2half_rn(d1 + bb.y);
                }
                {
                    int b = r1 >> 11, ss = r1 & (SEQ - 1);
                    __half* base = Ch + (((size_t)b * NHEAD + h) * HDIM + dd) * SEQ + ss;
                    base[0]   = __float2half_rn(d2 + bb.x);
                    base[SEQ] = __float2half_rn(d3 + bb.y);
                }
            } else {  // EPI_CTX: ctx_h[b][s][h*64 + c]
                __half* Ch = (__half*)Cv;
                int b = z >> 4, h = z & (NHEAD - 1);
                *(uint32_t*)(Ch + ((size_t)b * SEQ + r0) * DMODEL + h * HDIM + c) =
                    pack_h2(d0, d1);
                *(uint32_t*)(Ch + ((size_t)b * SEQ + r1) * DMODEL + h * HDIM + c) =
                    pack_h2(d2, d3);
            }
        }
    }
}

// ===================== transpose + fp16 round (Wq, Wfc) =====================
__global__ __launch_bounds__(256) void transpose_kernel(
    const float* __restrict__ in, __half* __restrict__ out)
{
    __shared__ float tile[32][33];
    int x0 = blockIdx.x * 32, y0 = blockIdx.y * 32;
    for (int i = threadIdx.y; i < 32; i += 8)
        tile[i][threadIdx.x] = in[(size_t)(y0 + i) * DMODEL + x0 + threadIdx.x];
    __syncthreads();
    for (int i = threadIdx.y; i < 32; i += 8)
        out[(size_t)(x0 + i) * DMODEL + y0 + threadIdx.x] =
            __float2half_rn(tile[threadIdx.x][i]);
}

// ===================== softmax / layernorm ==================================
__device__ __forceinline__ float warpMax(float v) {
#pragma unroll
    for (int o = 16; o > 0; o >>= 1) v = fmaxf(v, __shfl_xor_sync(0xffffffffu, v, o));
    return v;
}
__device__ __forceinline__ float warpSum(float v) {
#pragma unroll
    for (int o = 16; o > 0; o >>= 1) v += __shfl_xor_sync(0xffffffffu, v, o);
    return v;
}

__global__ __launch_bounds__(256) void softmax_kernel(float* __restrict__ attn)
{
    float* p = attn + (size_t)blockIdx.x * SEQ;
    const int tid = threadIdx.x;
    const int lane = tid & 31, wid = tid >> 5;
    __shared__ float sh[8];

    float4 a = *(float4*)(p + tid * 4);
    float4 b = *(float4*)(p + 1024 + tid * 4);

    float m = fmaxf(fmaxf(fmaxf(a.x, a.y), fmaxf(a.z, a.w)),
                    fmaxf(fmaxf(b.x, b.y), fmaxf(b.z, b.w)));
    m = warpMax(m);
    if (!lane) sh[wid] = m;
    __syncthreads();
    if (tid < 32) {
        float t = (tid < 8) ? sh[tid] : -3.4e38f;
        t = warpMax(t);
        if (!tid) sh[0] = t;
    }
    __syncthreads();
    m = sh[0];
    __syncthreads();

    a.x = __expf(a.x - m); a.y = __expf(a.y - m);
    a.z = __expf(a.z - m); a.w = __expf(a.w - m);
    b.x = __expf(b.x - m); b.y = __expf(b.y - m);
    b.z = __expf(b.z - m); b.w = __expf(b.w - m);

    float s = (a.x + a.y + a.z + a.w) + (b.x + b.y + b.z + b.w);
    s = warpSum(s);
    if (!lane) sh[wid] = s;
    __syncthreads();
    if (tid < 32) {
        float t = (tid < 8) ? sh[tid] : 0.f;
        t = warpSum(t);
        if (!tid) sh[0] = t;
    }
    __syncthreads();
    float inv = 1.f / sh[0];

    a.x *= inv; a.y *= inv; a.z *= inv; a.w *= inv;
    b.x *= inv; b.y *= inv; b.z *= inv; b.w *= inv;
    *(float4*)(p + tid * 4) = a;
    *(float4*)(p + 1024 + tid * 4) = b;
}

__global__ __launch_bounds__(256) void ln_kernel(
    const float* __restrict__ q, const float* __restrict__ fc,
    const float* __restrict__ gamma, const float* __restrict__ beta,
    float* __restrict__ out)
{
    const size_t base = (size_t)blockIdx.x * DMODEL;
    const int tid = threadIdx.x;
    const int lane = tid & 31, wid = tid >> 5;
    __shared__ float shs[8];
    __shared__ float shq[8];

    float4 xq = *(const float4*)(q + base + tid * 4);
    float4 xf = *(const float4*)(fc + base + tid * 4);
    float x0 = xq.x + xf.x, x1 = xq.y + xf.y, x2 = xq.z + xf.z, x3 = xq.w + xf.w;

    float s  = x0 + x1 + x2 + x3;
    float sq = x0 * x0 + x1 * x1 + x2 * x2 + x3 * x3;
    s = warpSum(s);
    sq = warpSum(sq);
    if (!lane) { shs[wid] = s; shq[wid] = sq; }
    __syncthreads();
    if (tid < 32) {
        float ts = (tid < 8) ? shs[tid] : 0.f;
        float tq = (tid < 8) ? shq[tid] : 0.f;
        ts = warpSum(ts);
        tq = warpSum(tq);
        if (!tid) { shs[0] = ts; shq[0] = tq; }
    }
    __syncthreads();

    const float inv_n = 1.f / DMODEL;
    float mu  = shs[0] * inv_n;
    float var = shq[0] * inv_n - mu * mu;
    float r = rsqrtf(var + 1e-6f);

    float4 gg = *(const float4*)(gamma + tid * 4);
    float4 be = *(const float4*)(beta + tid * 4);
    float4 y;
    y.x = (x0 - mu) * r * gg.x + be.x;
    y.y = (x1 - mu) * r * gg.y + be.y;
    y.z = (x2 - mu) * r * gg.z + be.z;
    y.w = (x3 - mu) * r * gg.w + be.w;
    *(float4*)(out + base + tid * 4) = y;
}

// ===================== launch ===============================================
extern "C" void kernel_launch(void* const* d_in, const int* in_sizes, int n_in,
                              void* d_out, int out_size)
{
    const float* q     = (const float*)d_in[0];
    const float* k     = (const float*)d_in[1];
    const float* v     = (const float*)d_in[2];
    const float* Wq    = (const float*)d_in[3];
    const float* bq    = (const float*)d_in[4];
    const float* Wfc   = (const float*)d_in[5];
    const float* bfc   = (const float*)d_in[6];
    const float* gamma = (const float*)d_in[7];
    const float* beta  = (const float*)d_in[8];

    float* out      = (float*)d_out;
    float* x_out    = out;
    float* attn_out = out + PROJ_ELEMS;

    float* base = nullptr;
    cudaGetSymbolAddress((void**)&base, g_scratch);
    __half* qh_h   = (__half*)(base);
    __half* kh_h   = (__half*)(base + PROJ_ELEMS / 2);
    __half* vhT_h  = (__half*)(base + 2 * (PROJ_ELEMS / 2));   // [B,H,DK,S]
    __half* ctx_h  = (__half*)(base + 3 * (PROJ_ELEMS / 2));
    float*  fcb    = base + 4 * (PROJ_ELEMS / 2);
    __half* WqT_h  = (__half*)(base + 4 * (PROJ_ELEMS / 2) + PROJ_ELEMS);
    __half* WfcT_h = (__half*)(base + 4 * (PROJ_ELEMS / 2) + PROJ_ELEMS + 512 * 1024);

    dim3 blk(256);

    transpose_kernel<<<dim3(32, 32), dim3(32, 8)>>>(Wq, WqT_h);
    transpose_kernel<<<dim3(32, 32), dim3(32, 8)>>>(Wfc, WfcT_h);

    // Projections (A raw fp32, B fp16)
    dim3 gproj(DMODEL / 128, NTOK / 128, 1);
    tc_gemm<128, EPI_PROJ,  true><<<gproj, blk>>>(q, WqT_h, bq, qh_h,  DMODEL, DMODEL, DMODEL);
    tc_gemm<128, EPI_PROJ,  true><<<gproj, blk>>>(k, WqT_h, bq, kh_h,  DMODEL, DMODEL, DMODEL);
    tc_gemm<128, EPI_PROJV, true><<<gproj, blk>>>(v, WqT_h, bq, vhT_h, DMODEL, DMODEL, DMODEL);

    // Scores (both operands fp16)
    dim3 gsc(SEQ / 128, SEQ / 128, NBH);
    tc_gemm<128, EPI_SCORES, false><<<gsc, blk>>>(qh_h, kh_h, nullptr, attn_out,
                                                  HDIM, HDIM, HDIM);

    softmax_kernel<<<NBH * SEQ, blk>>>(attn_out);

    // ctx (A = attn raw fp32, B = vhT fp16)
    dim3 gctx(1, SEQ / 128, NBH);
    tc_gemm<64, EPI_CTX, true><<<gctx, blk>>>(attn_out, vhT_h, nullptr, ctx_h,
                                              SEQ, SEQ, SEQ);

    // Out projection (A = ctx fp16, B = WfcT fp16)
    dim3 gfc(DMODEL / 128, NTOK / 128, 1);
    tc_gemm<128, EPI_PLAIN, false><<<gfc, blk>>>(ctx_h, WfcT_h, bfc, fcb,
                                                 DMODEL, DMODEL, DMODEL);

    ln_kernel<<<NTOK, blk>>>(q, fcb, gamma, beta, x_out);
}